// round 16
// baseline (speedup 1.0000x reference)
#include <cuda_runtime.h>

#define P 33                      // padded row stride for Wi in smem
#define LOG2E 1.4426950408889634f
// sV offsets
#define V_QWA 0
#define V_BA  32
#define V_QWB 64
#define V_BB  96
#define V_WF  128
#define V_BOAB 160
#define V_BOBA 192
#define V_BIAB 224
#define V_BIBA 320

__device__ __forceinline__ float tanhf_fast(float x) {
    float y; asm("tanh.approx.f32 %0, %1;" : "=f"(y) : "f"(x)); return y;
}

// S via tanh (sigmoid(x)=0.5*tanh(x/2)+0.5); T via exp2 + one fast divide.
__device__ __forceinline__ float elem_eval2(
    float a0, float a1, float a2, float b0, float b1,
    float C0, float C1, float C2, float C4l, float C5l, float C6h, float K0)
{
    const float db  = b1 - b0;
    const float dbh = 0.5f * db;
    const float t0 = tanhf_fast(fmaf(C0, a0, C1) * dbh);
    const float t1 = tanhf_fast(fmaf(C0, a1, C1) * dbh);
    const float t2 = tanhf_fast(fmaf(C0, a2, C1) * dbh);
    const float S  = fmaf(db * (1.f / 6.f), (t0 + t1 + t2) + 3.f, b0);

    const float d01 = a0 - a1, d21 = a2 - a1;
    const float wl0 = fmaf(C4l, b0, C5l);
    const float wl1 = fmaf(C4l, b1, C5l);
    const float u0 = exp2f(wl0 * d01), v0 = exp2f(wl0 * d21);
    const float u1 = exp2f(wl1 * d01), v1 = exp2f(wl1 * d21);
    const float n0 = fmaf(a0, u0, fmaf(a2, v0, a1));
    const float n1 = fmaf(a0, u1, fmaf(a2, v1, a1));
    const float dd0 = u0 + v0 + 1.f;
    const float dd1 = u1 + v1 + 1.f;
    const float Tn  = __fdividef(fmaf(n0, dd1, n1 * dd0), dd0 * dd1);

    const float y = fmaf(C2, S, fmaf(C6h, Tn, K0));
    return fmaxf(y, 0.01f * y);
}

// smem union: phase 1 = Wi staging (6336 floats), phase 2 = two 3072-float
// A tile buffers (double buffer; 6144 <= 6336).
__global__ void __launch_bounds__(512, 1)
fused_kernel(const float* __restrict__ gA, const float* __restrict__ gB,
             const float* __restrict__ WA, const float* __restrict__ bA,
             const float* __restrict__ WB, const float* __restrict__ bB,
             const float* __restrict__ Wi_AB, const float* __restrict__ bi_AB,
             const float* __restrict__ Wo_AB, const float* __restrict__ bo_AB,
             const float* __restrict__ Wi_BA, const float* __restrict__ bi_BA,
             const float* __restrict__ Wo_BA, const float* __restrict__ bo_BA,
             const float* __restrict__ Wf, const float* __restrict__ bf,
             float* __restrict__ out, int B, int nTiles)
{
    __shared__ float smem[6336];
    __shared__ float sV[417];
    __shared__ float sC[9];

    const int tid  = threadIdx.x;
    const int nA4  = (3 * B) >> 2;
    const float4* gA4 = (const float4*)gA;
    const float2* gB2 = (const float2*)gB;

    // balanced tile range for this block
    const int g    = gridDim.x;
    const int base = nTiles / g, rem = nTiles % g;
    const int bid  = blockIdx.x;
    const int count = base + (bid < rem ? 1 : 0);
    const int start = bid * base + (bid < rem ? bid : rem);

    const float4 z4 = make_float4(0.f, 0.f, 0.f, 0.f);
    const float2 z2 = make_float2(0.f, 0.f);

    // ---- prefetch first tile (in flight through all of setup) ----
    float4 Pa0 = z4, Pa1 = z4;
    float2 Bc0 = z2, Bc1 = z2;
    if (count > 0) {
        const int fa = start * 768 + tid;
        if (fa < nA4) Pa0 = gA4[fa];
        if (tid < 256 && fa + 512 < nA4) Pa1 = gA4[fa + 512];
        const int ib = (start << 10) + tid;
        if (ib < B)       Bc0 = gB2[ib];
        if (ib + 512 < B) Bc1 = gB2[ib + 512];
    }

    // ---- Wi staging into smem (coalesced, padded rows) + small vectors ----
    {
        const float4* src0 = (const float4*)Wi_AB;
        const float4* src1 = (const float4*)Wi_BA;
        for (int k = tid; k < 768; k += 512) {
            const int r = k >> 3, c = (k & 7) << 2;
            float4 v = src0[k];
            float* d = &smem[r * P + c];
            d[0] = v.x; d[1] = v.y; d[2] = v.z; d[3] = v.w;
            v = src1[k];
            d = &smem[96 * P + r * P + c];
            d[0] = v.x; d[1] = v.y; d[2] = v.z; d[3] = v.w;
        }
        if (tid < 32)              sV[V_QWA + tid]        = WA[tid];
        else if (tid < 64)         sV[V_BA  + tid - 32]   = bA[tid - 32];
        else if (tid < 96)         sV[V_QWB + tid - 64]   = WB[tid - 64];
        else if (tid < 128)        sV[V_BB  + tid - 96]   = bB[tid - 96];
        else if (tid < 160)        sV[V_WF  + tid - 128]  = Wf[tid - 128];
        else if (tid < 192)        sV[V_BOAB + tid - 160] = bo_AB[tid - 160];
        else if (tid < 224)        sV[V_BOBA + tid - 192] = bo_BA[tid - 192];
        else if (tid < 320)        sV[V_BIAB + tid - 224] = bi_AB[tid - 224];
        else if (tid < 416)        sV[V_BIBA + tid - 320] = bi_BA[tid - 320];
        else if (tid == 416)       sC[8] = bf[0];
    }
    __syncthreads();

    // ---- phase B: 2 warps derive the 8 scalar constants ----
    if (tid < 64) {
        const int dir = tid >> 5;
        const int e   = tid & 31;
        const int qw = dir ? V_QWB : V_QWA;
        const int qb = dir ? V_BB  : V_BA;
        const int kw = dir ? V_QWA : V_QWB;
        const int kb = dir ? V_BA  : V_BB;
        const int bi = dir ? V_BIBA : V_BIAB;
        const int bo = dir ? V_BOBA : V_BOAB;
        const float* Wo = dir ? Wo_BA : Wo_AB;

        const float* wbase = &smem[dir * 96 * P];
        const float* rq = &wbase[e * P];
        const float* rk = &wbase[(32 + e) * P];
        const float* rv = &wbase[(64 + e) * P];

        float uq = 0.f, cq = 0.f, uk = 0.f, uv = 0.f, cv = 0.f, gg = 0.f;
        #pragma unroll
        for (int d = 0; d < 32; ++d) {
            const float wq = rq[d], wkv = rk[d], wvv = rv[d];
            uq = fmaf(wq,  sV[qw + d], uq);
            cq = fmaf(wq,  sV[qb + d], cq);
            uk = fmaf(wkv, sV[kw + d], uk);
            uv = fmaf(wvv, sV[kw + d], uv);
            cv = fmaf(wvv, sV[kb + d], cv);
            gg = fmaf(sV[V_WF + d], Wo[d * 32 + e], gg);
        }
        cq += sV[bi + e];
        cv += sV[bi + 64 + e];

        float alpha = uq * uk;
        float gamma = cq * uk;
        float kk    = gg * uv;
        float rr    = fmaf(sV[V_WF + e], sV[bo + e], gg * cv);
        #pragma unroll
        for (int off = 16; off; off >>= 1) {
            alpha += __shfl_xor_sync(0xffffffffu, alpha, off);
            gamma += __shfl_xor_sync(0xffffffffu, gamma, off);
            kk    += __shfl_xor_sync(0xffffffffu, kk, off);
            rr    += __shfl_xor_sync(0xffffffffu, rr, off);
        }
        if (e == 0) {
            const float inv_sqrtE = 0.17677669529663688f;  // 1/sqrt(32)
            sC[dir * 4 + 0] = alpha * inv_sqrtE;
            sC[dir * 4 + 1] = gamma * inv_sqrtE;
            sC[dir * 4 + 2] = 0.5f * kk;
            sC[dir * 4 + 3] = rr;
        }
    }
    __syncthreads();

    const float C0  = sC[0], C1 = sC[1];
    const float C2  = sC[2];
    const float C4l = sC[4] * LOG2E, C5l = sC[5] * LOG2E;
    const float C6h = 0.5f * sC[6];
    const float K0  = fmaf(0.5f, sC[3] + sC[7], sC[8]);

    // ---- persistent tile loop: smem now the A double buffer ----
    int cur = 0;
    for (int k = 0; k < count; ++k) {
        const int t  = start + k;
        const int Et = t << 10;
        float* buf = smem + cur * 3072;

        // dump prefetched A tile into buf[cur]
        ((float4*)buf)[tid] = Pa0;
        if (tid < 256) ((float4*)buf)[512 + tid] = Pa1;

        // prefetch tile t+1 (A and B) — overlaps this tile's compute
        float2 Bn0 = z2, Bn1 = z2;
        if (k + 1 < count) {
            const int fa = (t + 1) * 768 + tid;
            Pa0 = (fa < nA4) ? gA4[fa] : z4;
            if (tid < 256) Pa1 = (fa + 512 < nA4) ? gA4[fa + 512] : z4;
            const int ib = ((t + 1) << 10) + tid;
            if (ib < B)       Bn0 = gB2[ib];
            if (ib + 512 < B) Bn1 = gB2[ib + 512];
        }
        __syncthreads();

        // compute 2 elements from buf (stride-3 conflict-free LDS)
        {
            const int i0 = tid, i1 = 512 + tid;
            const int x0 = Et + i0, x1 = Et + i1;
            if (x0 < B)
                out[x0] = elem_eval2(buf[3 * i0], buf[3 * i0 + 1], buf[3 * i0 + 2],
                                     Bc0.x, Bc0.y, C0, C1, C2, C4l, C5l, C6h, K0);
            if (x1 < B)
                out[x1] = elem_eval2(buf[3 * i1], buf[3 * i1 + 1], buf[3 * i1 + 2],
                                     Bc1.x, Bc1.y, C0, C1, C2, C4l, C5l, C6h, K0);
        }
        Bc0 = Bn0; Bc1 = Bn1;
        cur ^= 1;
    }

    // scalar tail if 3*B isn't float4-aligned (dead for B = 524288)
    if ((3 * B) & 3) {
        if (bid == 0 && tid == 0) {
            for (int idx = (nA4 * 4) / 3; idx < B; ++idx) {
                out[idx] = elem_eval2(
                    gA[3 * idx], gA[3 * idx + 1], gA[3 * idx + 2],
                    gB[2 * idx], gB[2 * idx + 1],
                    C0, C1, C2, C4l, C5l, C6h, K0);
            }
        }
    }
}

extern "C" void kernel_launch(void* const* d_in, const int* in_sizes, int n_in,
                              void* d_out, int out_size)
{
    const float* gA    = (const float*)d_in[0];   // [B,3]
    const float* gB    = (const float*)d_in[1];   // [B,2]
    const float* WA    = (const float*)d_in[2];   // [32,1]
    const float* bA    = (const float*)d_in[3];   // [32]
    const float* WB    = (const float*)d_in[4];
    const float* bB    = (const float*)d_in[5];
    const float* Wi_AB = (const float*)d_in[6];   // [96,32]
    const float* bi_AB = (const float*)d_in[7];   // [96]
    const float* Wo_AB = (const float*)d_in[8];   // [32,32]
    const float* bo_AB = (const float*)d_in[9];   // [32]
    const float* Wi_BA = (const float*)d_in[10];
    const float* bi_BA = (const float*)d_in[11];
    const float* Wo_BA = (const float*)d_in[12];
    const float* bo_BA = (const float*)d_in[13];
    const float* Wf    = (const float*)d_in[14];  // [1,32]
    const float* bf    = (const float*)d_in[15];  // [1]

    const int B      = in_sizes[0] / 3;
    const int nTiles = (B + 1023) >> 10;
    int grid = nTiles < 148 ? nTiles : 148;
    if (grid < 1) grid = 1;

    fused_kernel<<<grid, 512>>>(gA, gB, WA, bA, WB, bB,
                                Wi_AB, bi_AB, Wo_AB, bo_AB,
                                Wi_BA, bi_BA, Wo_BA, bo_BA,
                                Wf, bf, (float*)d_out, B, nTiles);
}